// round 1
// baseline (speedup 1.0000x reference)
#include <cuda_runtime.h>
#include <cuda_bf16.h>

#define N_NODES 100000
#define N_EDGES 1000000
#define D 64
#define ALPHA 10.0f

// Scratch (device globals: allocation-free per harness rules)
__device__ float g_deg[N_NODES];
__device__ float g_norm[N_NODES];
__device__ float g_hs0[N_NODES * D];   // norm * feats
__device__ float g_S1[N_NODES * D];    // segment_sum(hs0[src] -> dst)
__device__ float g_S2[N_NODES * D];    // segment_sum(norm^2*S1[src] -> dst)

__device__ __forceinline__ void red4(float* p, float4 v) {
    asm volatile("red.global.add.v4.f32 [%0], {%1,%2,%3,%4};"
                 :: "l"(p), "f"(v.x), "f"(v.y), "f"(v.z), "f"(v.w)
                 : "memory");
}

// ---------------- zero scratch accumulators ----------------
// total float4s: deg 25000 + S1 1600000 + S2 1600000 = 3225000
__global__ void zero_kernel() {
    int i = blockIdx.x * blockDim.x + threadIdx.x;
    if (i >= 3225000) return;
    float4 z = make_float4(0.f, 0.f, 0.f, 0.f);
    if (i < 25000) {
        ((float4*)g_deg)[i] = z;
    } else if (i < 1625000) {
        ((float4*)g_S1)[i - 25000] = z;
    } else {
        ((float4*)g_S2)[i - 1625000] = z;
    }
}

// ---------------- degree accumulation ----------------
__global__ void deg_kernel(const int* __restrict__ dst,
                           const int* __restrict__ e_feat,
                           const float* __restrict__ edge_weight) {
    int e = blockIdx.x * blockDim.x + threadIdx.x;
    if (e >= N_EDGES) return;
    float x = edge_weight[e_feat[e] - 1] * ALPHA;
    float w = x > 0.f ? x : 0.01f * x;   // leaky_relu, slope 0.01
    atomicAdd(&g_deg[dst[e]], w);
}

// ---------------- norm + pre-scaled feats ----------------
// 16 threads per node (one float4 each)
__global__ void norm_hs0_kernel(const float* __restrict__ feats) {
    int t = blockIdx.x * blockDim.x + threadIdx.x;  // < N_NODES*16
    int n = t >> 4, c = t & 15;
    float nm = rsqrtf(fmaxf(g_deg[n], 1.0f));
    if (c == 0) g_norm[n] = nm;
    float4 v = ((const float4*)feats)[n * 16 + c];
    v.x *= nm; v.y *= nm; v.z *= nm; v.w *= nm;
    ((float4*)g_hs0)[n * 16 + c] = v;
}

// ---------------- SpMM pass 1: S1[dst] += hs0[src] ----------------
// 16 threads per edge (one float4 each), 16M threads total
__global__ void spmm1_kernel(const int* __restrict__ src,
                             const int* __restrict__ dst) {
    int t = blockIdx.x * blockDim.x + threadIdx.x;
    int e = t >> 4, c = t & 15;
    int s = src[e], d = dst[e];
    float4 v = ((const float4*)g_hs0)[s * 16 + c];
    red4((float*)&((float4*)g_S1)[d * 16 + c], v);
}

// ---------------- SpMM pass 2: S2[dst] += norm[src]^2 * S1[src] ----
__global__ void spmm2_kernel(const int* __restrict__ src,
                             const int* __restrict__ dst) {
    int t = blockIdx.x * blockDim.x + threadIdx.x;
    int e = t >> 4, c = t & 15;
    int s = src[e], d = dst[e];
    float nm = g_norm[s];
    float n2 = nm * nm;
    float4 v = ((const float4*)g_S1)[s * 16 + c];
    v.x *= n2; v.y *= n2; v.z *= n2; v.w *= n2;
    red4((float*)&((float4*)g_S2)[d * 16 + c], v);
}

// ---------------- fused 3x GEMM (64x64 each) + norm epilogue ------
// Block: 64 nodes, 128 threads. Thread: 4 nodes x 8 outs.
// sH stored transposed [k][node] so per k-step: 3x LDS.128 + 32 FFMA.
__global__ __launch_bounds__(128) void gemm_kernel(
    const float* __restrict__ feats,
    const float* __restrict__ w0,
    const float* __restrict__ w1,
    const float* __restrict__ w2,
    float* __restrict__ out) {
    __shared__ float sW[D][D];      // [k][j]
    __shared__ float sH[D][D];      // [k][node]

    int tid = threadIdx.x;
    int nb = blockIdx.x * 64;
    int q = tid & 15;     // node-quad: nodes q*4 .. q*4+3
    int g = tid >> 4;     // out-group: outs g*8 .. g*8+7

    const float* Ws[3] = {w0, w1, w2};

#pragma unroll 1
    for (int m = 0; m < 3; m++) {
        // load W_m (4096 floats, 8 float4 per thread)
        const float4* wf = (const float4*)Ws[m];
#pragma unroll
        for (int r = 0; r < 8; r++)
            ((float4*)sW)[tid + r * 128] = wf[tid + r * 128];

        // load H tile transposed, with fused norm scale
        int n = tid >> 1;        // 0..63
        int half = tid & 1;
        int gn = nb + n;
        const float* srcp = (m == 0) ? feats : (m == 1) ? g_S1 : g_S2;
        float sc = 1.0f;
        if (m > 0) sc = (gn < N_NODES) ? g_norm[gn] : 0.0f;
        bool ok = (gn < N_NODES);
#pragma unroll
        for (int r = 0; r < 8; r++) {
            int c = half * 8 + r;
            float4 v = ok ? ((const float4*)srcp)[gn * 16 + c]
                          : make_float4(0.f, 0.f, 0.f, 0.f);
            v.x *= sc; v.y *= sc; v.z *= sc; v.w *= sc;
            sH[4 * c + 0][n] = v.x;
            sH[4 * c + 1][n] = v.y;
            sH[4 * c + 2][n] = v.z;
            sH[4 * c + 3][n] = v.w;
        }
        __syncthreads();

        float acc[4][8];
#pragma unroll
        for (int i = 0; i < 4; i++)
#pragma unroll
            for (int j = 0; j < 8; j++) acc[i][j] = 0.f;

#pragma unroll 8
        for (int k = 0; k < D; k++) {
            float4 hv  = *(const float4*)&sH[k][q * 4];
            float4 wa  = *(const float4*)&sW[k][g * 8];
            float4 wb  = *(const float4*)&sW[k][g * 8 + 4];
            float h[4] = {hv.x, hv.y, hv.z, hv.w};
            float w[8] = {wa.x, wa.y, wa.z, wa.w, wb.x, wb.y, wb.z, wb.w};
#pragma unroll
            for (int i = 0; i < 4; i++)
#pragma unroll
                for (int j = 0; j < 8; j++)
                    acc[i][j] = fmaf(h[i], w[j], acc[i][j]);
        }

        // store: out[node][m*64 + g*8 .. +7]
#pragma unroll
        for (int i = 0; i < 4; i++) {
            int gn2 = nb + q * 4 + i;
            if (gn2 < N_NODES) {
                float* op = out + (size_t)gn2 * 192 + m * 64 + g * 8;
                *(float4*)op       = make_float4(acc[i][0], acc[i][1], acc[i][2], acc[i][3]);
                *(float4*)(op + 4) = make_float4(acc[i][4], acc[i][5], acc[i][6], acc[i][7]);
            }
        }
        __syncthreads();
    }
}

extern "C" void kernel_launch(void* const* d_in, const int* in_sizes, int n_in,
                              void* d_out, int out_size) {
    const float* feats       = (const float*)d_in[0];
    const float* edge_weight = (const float*)d_in[1];
    const float* w0          = (const float*)d_in[2];
    const float* w1          = (const float*)d_in[3];
    const float* w2          = (const float*)d_in[4];
    const int*   src         = (const int*)d_in[5];
    const int*   dst         = (const int*)d_in[6];
    const int*   e_feat      = (const int*)d_in[7];
    float* out = (float*)d_out;

    zero_kernel<<<(3225000 + 255) / 256, 256>>>();
    deg_kernel<<<(N_EDGES + 255) / 256, 256>>>(dst, e_feat, edge_weight);
    norm_hs0_kernel<<<(N_NODES * 16) / 256, 256>>>(feats);
    spmm1_kernel<<<(N_EDGES * 16) / 256, 256>>>(src, dst);
    spmm2_kernel<<<(N_EDGES * 16) / 256, 256>>>(src, dst);
    gemm_kernel<<<(N_NODES + 63) / 64, 128>>>(feats, w0, w1, w2, out);
}

// round 2
// speedup vs baseline: 1.2567x; 1.2567x over previous
#include <cuda_runtime.h>
#include <cuda_bf16.h>

#define N_NODES 100000
#define N_EDGES 1000000
#define D 64
#define ALPHA 10.0f
#define NBLK_SCAN 391   // ceil(100000/256)

// ---------------- scratch (device globals) ----------------
__device__ int   g_cnt[N_NODES];
__device__ int   g_row[N_NODES];
__device__ int   g_cur[N_NODES];
__device__ int   g_bsum[512];
__device__ int   g_perm[N_EDGES];          // src ids, sorted by dst
__device__ float g_deg[N_NODES];
__device__ float g_norm[N_NODES];
__device__ float g_hs0[N_NODES * D];       // norm * feats          (gather1 input)
__device__ float g_S1n[N_NODES * D];       // norm   * S1           (gemm m=1 input)
__device__ float g_hs1[N_NODES * D];       // norm^2 * S1           (gather2 input)
__device__ float g_S2n[N_NODES * D];       // norm   * S2           (gemm m=2 input)

// ---------------- zero counts + deg ----------------
__global__ void zero_kernel() {
    int i = blockIdx.x * blockDim.x + threadIdx.x;   // < 50000
    if (i < 25000) {
        ((int4*)g_cnt)[i] = make_int4(0, 0, 0, 0);
    } else if (i < 50000) {
        ((float4*)g_deg)[i - 25000] = make_float4(0.f, 0.f, 0.f, 0.f);
    }
}

// ---------------- histogram + weighted degree ----------------
__global__ void hist_kernel(const int* __restrict__ dst,
                            const int* __restrict__ e_feat,
                            const float* __restrict__ edge_weight) {
    int e = blockIdx.x * blockDim.x + threadIdx.x;
    if (e >= N_EDGES) return;
    int d = dst[e];
    atomicAdd(&g_cnt[d], 1);
    float x = edge_weight[e_feat[e] - 1] * ALPHA;
    float w = x > 0.f ? x : 0.01f * x;   // leaky_relu
    atomicAdd(&g_deg[d], w);
}

// ---------------- scan phase A: per-block sums ----------------
__global__ void scanA_kernel() {
    __shared__ int sm[256];
    int i = blockIdx.x * 256 + threadIdx.x;
    int v = (i < N_NODES) ? g_cnt[i] : 0;
    sm[threadIdx.x] = v;
    __syncthreads();
    for (int o = 128; o > 0; o >>= 1) {
        if (threadIdx.x < o) sm[threadIdx.x] += sm[threadIdx.x + o];
        __syncthreads();
    }
    if (threadIdx.x == 0) g_bsum[blockIdx.x] = sm[0];
}

// ---------------- scan phase B: scan block sums (single block 512) ----
__global__ void scanB_kernel() {
    int tid = threadIdx.x;
    int v = (tid < NBLK_SCAN) ? g_bsum[tid] : 0;
    unsigned lane = tid & 31, wid = tid >> 5;
    int x = v;
    for (int o = 1; o < 32; o <<= 1) {
        int y = __shfl_up_sync(0xffffffffu, x, o);
        if (lane >= o) x += y;
    }
    __shared__ int ws[16];
    if (lane == 31) ws[wid] = x;
    __syncthreads();
    if (wid == 0) {
        int s = (lane < 16) ? ws[lane] : 0;
        for (int o = 1; o < 16; o <<= 1) {
            int y = __shfl_up_sync(0xffffffffu, s, o);
            if (lane >= o) s += y;
        }
        if (lane < 16) ws[lane] = s;
    }
    __syncthreads();
    int excl = x - v + (wid ? ws[wid - 1] : 0);
    if (tid < NBLK_SCAN) g_bsum[tid] = excl;
}

// ---------------- scan phase C: block scan + offset, write row & cursor --
__global__ void scanC_kernel() {
    int i = blockIdx.x * 256 + threadIdx.x;
    int tid = threadIdx.x;
    int v = (i < N_NODES) ? g_cnt[i] : 0;
    unsigned lane = tid & 31, wid = tid >> 5;
    int x = v;
    for (int o = 1; o < 32; o <<= 1) {
        int y = __shfl_up_sync(0xffffffffu, x, o);
        if (lane >= o) x += y;
    }
    __shared__ int ws[8];
    if (lane == 31) ws[wid] = x;
    __syncthreads();
    if (wid == 0) {
        int s = (lane < 8) ? ws[lane] : 0;
        for (int o = 1; o < 8; o <<= 1) {
            int y = __shfl_up_sync(0xffffffffu, s, o);
            if (lane >= o) s += y;
        }
        if (lane < 8) ws[lane] = s;
    }
    __syncthreads();
    int excl = x - v + (wid ? ws[wid - 1] : 0) + g_bsum[blockIdx.x];
    if (i < N_NODES) {
        g_row[i] = excl;
        g_cur[i] = excl;
    }
}

// ---------------- scatter: build perm (src sorted by dst) ----------------
__global__ void scatter_kernel(const int* __restrict__ src,
                               const int* __restrict__ dst) {
    int e = blockIdx.x * blockDim.x + threadIdx.x;
    if (e >= N_EDGES) return;
    int p = atomicAdd(&g_cur[dst[e]], 1);
    g_perm[p] = src[e];
}

// ---------------- norm + pre-scaled feats ----------------
__global__ void norm_hs0_kernel(const float* __restrict__ feats) {
    int t = blockIdx.x * blockDim.x + threadIdx.x;  // < N_NODES*16
    int n = t >> 4, c = t & 15;
    float nm = rsqrtf(fmaxf(g_deg[n], 1.0f));
    if (c == 0) g_norm[n] = nm;
    float4 v = ((const float4*)feats)[n * 16 + c];
    v.x *= nm; v.y *= nm; v.z *= nm; v.w *= nm;
    ((float4*)g_hs0)[n * 16 + c] = v;
}

// ---------------- gather pass 1: S1 = A*hs0 ; emit norm*S1 and norm^2*S1 --
__global__ __launch_bounds__(256) void gather1_kernel() {
    int t = blockIdx.x * 256 + threadIdx.x;
    int n = t >> 4, c = t & 15;       // 16 threads per node
    int e = g_row[n];
    int eend = e + g_cnt[n];
    float4 acc = make_float4(0.f, 0.f, 0.f, 0.f);
    const float4* H = (const float4*)g_hs0;
    for (; e + 1 < eend; e += 2) {
        int s0 = g_perm[e], s1 = g_perm[e + 1];
        float4 a = H[s0 * 16 + c];
        float4 b = H[s1 * 16 + c];
        acc.x += a.x; acc.y += a.y; acc.z += a.z; acc.w += a.w;
        acc.x += b.x; acc.y += b.y; acc.z += b.z; acc.w += b.w;
    }
    if (e < eend) {
        int s0 = g_perm[e];
        float4 a = H[s0 * 16 + c];
        acc.x += a.x; acc.y += a.y; acc.z += a.z; acc.w += a.w;
    }
    float nm = g_norm[n];
    float4 v1 = make_float4(acc.x * nm, acc.y * nm, acc.z * nm, acc.w * nm);
    ((float4*)g_S1n)[n * 16 + c] = v1;
    float4 v2 = make_float4(v1.x * nm, v1.y * nm, v1.z * nm, v1.w * nm);
    ((float4*)g_hs1)[n * 16 + c] = v2;
}

// ---------------- gather pass 2: S2 = A*hs1 ; emit norm*S2 ----------------
__global__ __launch_bounds__(256) void gather2_kernel() {
    int t = blockIdx.x * 256 + threadIdx.x;
    int n = t >> 4, c = t & 15;
    int e = g_row[n];
    int eend = e + g_cnt[n];
    float4 acc = make_float4(0.f, 0.f, 0.f, 0.f);
    const float4* H = (const float4*)g_hs1;
    for (; e + 1 < eend; e += 2) {
        int s0 = g_perm[e], s1 = g_perm[e + 1];
        float4 a = H[s0 * 16 + c];
        float4 b = H[s1 * 16 + c];
        acc.x += a.x; acc.y += a.y; acc.z += a.z; acc.w += a.w;
        acc.x += b.x; acc.y += b.y; acc.z += b.z; acc.w += b.w;
    }
    if (e < eend) {
        int s0 = g_perm[e];
        float4 a = H[s0 * 16 + c];
        acc.x += a.x; acc.y += a.y; acc.z += a.z; acc.w += a.w;
    }
    float nm = g_norm[n];
    ((float4*)g_S2n)[n * 16 + c] =
        make_float4(acc.x * nm, acc.y * nm, acc.z * nm, acc.w * nm);
}

// ---------------- fused 3x GEMM (64x64 each) ----------------
__global__ __launch_bounds__(128) void gemm_kernel(
    const float* __restrict__ feats,
    const float* __restrict__ w0,
    const float* __restrict__ w1,
    const float* __restrict__ w2,
    float* __restrict__ out) {
    __shared__ float sW[D][D];      // [k][j]
    __shared__ float sH[D][D];      // [k][node]

    int tid = threadIdx.x;
    int nb = blockIdx.x * 64;
    int q = tid & 15;     // node-quad
    int g = tid >> 4;     // out-group

    const float* Ws[3] = {w0, w1, w2};

#pragma unroll 1
    for (int m = 0; m < 3; m++) {
        const float4* wf = (const float4*)Ws[m];
#pragma unroll
        for (int r = 0; r < 8; r++)
            ((float4*)sW)[tid + r * 128] = wf[tid + r * 128];

        int n = tid >> 1;
        int half = tid & 1;
        int gn = nb + n;
        const float* srcp = (m == 0) ? feats : (m == 1) ? g_S1n : g_S2n;
        bool ok = (gn < N_NODES);
#pragma unroll
        for (int r = 0; r < 8; r++) {
            int c = half * 8 + r;
            float4 v = ok ? ((const float4*)srcp)[gn * 16 + c]
                          : make_float4(0.f, 0.f, 0.f, 0.f);
            sH[4 * c + 0][n] = v.x;
            sH[4 * c + 1][n] = v.y;
            sH[4 * c + 2][n] = v.z;
            sH[4 * c + 3][n] = v.w;
        }
        __syncthreads();

        float acc[4][8];
#pragma unroll
        for (int i = 0; i < 4; i++)
#pragma unroll
            for (int j = 0; j < 8; j++) acc[i][j] = 0.f;

#pragma unroll 8
        for (int k = 0; k < D; k++) {
            float4 hv  = *(const float4*)&sH[k][q * 4];
            float4 wa  = *(const float4*)&sW[k][g * 8];
            float4 wb  = *(const float4*)&sW[k][g * 8 + 4];
            float h[4] = {hv.x, hv.y, hv.z, hv.w};
            float w[8] = {wa.x, wa.y, wa.z, wa.w, wb.x, wb.y, wb.z, wb.w};
#pragma unroll
            for (int i = 0; i < 4; i++)
#pragma unroll
                for (int j = 0; j < 8; j++)
                    acc[i][j] = fmaf(h[i], w[j], acc[i][j]);
        }

#pragma unroll
        for (int i = 0; i < 4; i++) {
            int gn2 = nb + q * 4 + i;
            if (gn2 < N_NODES) {
                float* op = out + (size_t)gn2 * 192 + m * 64 + g * 8;
                *(float4*)op       = make_float4(acc[i][0], acc[i][1], acc[i][2], acc[i][3]);
                *(float4*)(op + 4) = make_float4(acc[i][4], acc[i][5], acc[i][6], acc[i][7]);
            }
        }
        __syncthreads();
    }
}

extern "C" void kernel_launch(void* const* d_in, const int* in_sizes, int n_in,
                              void* d_out, int out_size) {
    const float* feats       = (const float*)d_in[0];
    const float* edge_weight = (const float*)d_in[1];
    const float* w0          = (const float*)d_in[2];
    const float* w1          = (const float*)d_in[3];
    const float* w2          = (const float*)d_in[4];
    const int*   src         = (const int*)d_in[5];
    const int*   dst         = (const int*)d_in[6];
    const int*   e_feat      = (const int*)d_in[7];
    float* out = (float*)d_out;

    zero_kernel<<<(50000 + 255) / 256, 256>>>();
    hist_kernel<<<(N_EDGES + 255) / 256, 256>>>(dst, e_feat, edge_weight);
    scanA_kernel<<<NBLK_SCAN, 256>>>();
    scanB_kernel<<<1, 512>>>();
    scanC_kernel<<<NBLK_SCAN, 256>>>();
    scatter_kernel<<<(N_EDGES + 255) / 256, 256>>>(src, dst);
    norm_hs0_kernel<<<(N_NODES * 16) / 256, 256>>>(feats);
    gather1_kernel<<<(N_NODES * 16) / 256, 256>>>();
    gather2_kernel<<<(N_NODES * 16) / 256, 256>>>();
    gemm_kernel<<<(N_NODES + 63) / 64, 128>>>(feats, w0, w1, w2, out);
}

// round 4
// speedup vs baseline: 1.4596x; 1.1614x over previous
#include <cuda_runtime.h>
#include <cuda_bf16.h>
#include <cstdint>

#define N_NODES 100000
#define N_EDGES 1000000
#define D 64
#define ALPHA 10.0f
#define NBLK_SCAN 391    // ceil(100000/256)
#define GTILES 1563      // ceil(100000/64)

// ---------------- scratch (device globals) ----------------
__device__ int   g_cnt[N_NODES];
__device__ int   g_row[N_NODES];
__device__ int   g_cur[N_NODES];
__device__ int   g_bsum[512];
__device__ int   g_perm[N_EDGES];          // src ids, sorted by dst
__device__ float g_deg[N_NODES];
__device__ float g_norm[N_NODES];
__device__ float g_hs0[N_NODES * D];       // norm * feats          (gather1 input)
__device__ float g_S1n[N_NODES * D];       // norm   * S1           (gemm m=1 input)
__device__ float g_hs1[N_NODES * D];       // norm^2 * S1           (gather2 input)
__device__ float g_S2n[N_NODES * D];       // norm   * S2           (gemm m=2 input)

// ---------------- zero counts + deg ----------------
__global__ void zero_kernel() {
    int i = blockIdx.x * blockDim.x + threadIdx.x;   // < 50000
    if (i < 25000) {
        ((int4*)g_cnt)[i] = make_int4(0, 0, 0, 0);
    } else if (i < 50000) {
        ((float4*)g_deg)[i - 25000] = make_float4(0.f, 0.f, 0.f, 0.f);
    }
}

// ---------------- histogram + weighted degree ----------------
__global__ void hist_kernel(const int* __restrict__ dst,
                            const int* __restrict__ e_feat,
                            const float* __restrict__ edge_weight) {
    int e = blockIdx.x * blockDim.x + threadIdx.x;
    if (e >= N_EDGES) return;
    int d = dst[e];
    atomicAdd(&g_cnt[d], 1);
    float x = edge_weight[e_feat[e] - 1] * ALPHA;
    float w = x > 0.f ? x : 0.01f * x;   // leaky_relu
    atomicAdd(&g_deg[d], w);
}

// ---------------- scan phase A: per-block sums ----------------
__global__ void scanA_kernel() {
    __shared__ int sm[256];
    int i = blockIdx.x * 256 + threadIdx.x;
    int v = (i < N_NODES) ? g_cnt[i] : 0;
    sm[threadIdx.x] = v;
    __syncthreads();
    for (int o = 128; o > 0; o >>= 1) {
        if (threadIdx.x < o) sm[threadIdx.x] += sm[threadIdx.x + o];
        __syncthreads();
    }
    if (threadIdx.x == 0) g_bsum[blockIdx.x] = sm[0];
}

// ---------------- scan phase C: block offset via reduction + intra scan ---
__global__ void scanC_kernel() {
    int tid = threadIdx.x;
    int acc = 0;
    for (int j = tid; j < blockIdx.x; j += 256) acc += g_bsum[j];
    __shared__ int red[256];
    red[tid] = acc;
    __syncthreads();
    for (int o = 128; o > 0; o >>= 1) {
        if (tid < o) red[tid] += red[tid + o];
        __syncthreads();
    }
    int block_off = red[0];
    __syncthreads();

    int i = blockIdx.x * 256 + tid;
    int v = (i < N_NODES) ? g_cnt[i] : 0;
    unsigned lane = tid & 31, wid = tid >> 5;
    int x = v;
    for (int o = 1; o < 32; o <<= 1) {
        int y = __shfl_up_sync(0xffffffffu, x, o);
        if (lane >= o) x += y;
    }
    __shared__ int ws[8];
    if (lane == 31) ws[wid] = x;
    __syncthreads();
    if (wid == 0) {
        int s = (lane < 8) ? ws[lane] : 0;
        for (int o = 1; o < 8; o <<= 1) {
            int y = __shfl_up_sync(0xffffffffu, s, o);
            if (lane >= o) s += y;
        }
        if (lane < 8) ws[lane] = s;
    }
    __syncthreads();
    int excl = x - v + (wid ? ws[wid - 1] : 0) + block_off;
    if (i < N_NODES) {
        g_row[i] = excl;
        g_cur[i] = excl;
    }
}

// ---------------- scatter: build perm (src sorted by dst) ----------------
__global__ void scatter_kernel(const int* __restrict__ src,
                               const int* __restrict__ dst) {
    int e = blockIdx.x * blockDim.x + threadIdx.x;
    if (e >= N_EDGES) return;
    int p = atomicAdd(&g_cur[dst[e]], 1);
    g_perm[p] = src[e];
}

// ---------------- norm + pre-scaled feats ----------------
__global__ void norm_hs0_kernel(const float* __restrict__ feats) {
    int t = blockIdx.x * blockDim.x + threadIdx.x;  // < N_NODES*16
    int n = t >> 4, c = t & 15;
    float nm = rsqrtf(fmaxf(g_deg[n], 1.0f));
    if (c == 0) g_norm[n] = nm;
    float4 v = ((const float4*)feats)[n * 16 + c];
    v.x *= nm; v.y *= nm; v.z *= nm; v.w *= nm;
    ((float4*)g_hs0)[n * 16 + c] = v;
}

// ---------------- gather pass 1 ----------------
__global__ __launch_bounds__(256) void gather1_kernel() {
    int t = blockIdx.x * 256 + threadIdx.x;
    int n = t >> 4, c = t & 15;       // 16 threads per node
    int e = g_row[n];
    int eend = e + g_cnt[n];
    float4 acc = make_float4(0.f, 0.f, 0.f, 0.f);
    const float4* H = (const float4*)g_hs0;
    for (; e + 1 < eend; e += 2) {
        int s0 = g_perm[e], s1 = g_perm[e + 1];
        float4 a = H[s0 * 16 + c];
        float4 b = H[s1 * 16 + c];
        acc.x += a.x; acc.y += a.y; acc.z += a.z; acc.w += a.w;
        acc.x += b.x; acc.y += b.y; acc.z += b.z; acc.w += b.w;
    }
    if (e < eend) {
        int s0 = g_perm[e];
        float4 a = H[s0 * 16 + c];
        acc.x += a.x; acc.y += a.y; acc.z += a.z; acc.w += a.w;
    }
    float nm = g_norm[n];
    float4 v1 = make_float4(acc.x * nm, acc.y * nm, acc.z * nm, acc.w * nm);
    ((float4*)g_S1n)[n * 16 + c] = v1;
    float4 v2 = make_float4(v1.x * nm, v1.y * nm, v1.z * nm, v1.w * nm);
    ((float4*)g_hs1)[n * 16 + c] = v2;
}

// ---------------- gather pass 2 ----------------
__global__ __launch_bounds__(256) void gather2_kernel() {
    int t = blockIdx.x * 256 + threadIdx.x;
    int n = t >> 4, c = t & 15;
    int e = g_row[n];
    int eend = e + g_cnt[n];
    float4 acc = make_float4(0.f, 0.f, 0.f, 0.f);
    const float4* H = (const float4*)g_hs1;
    for (; e + 1 < eend; e += 2) {
        int s0 = g_perm[e], s1 = g_perm[e + 1];
        float4 a = H[s0 * 16 + c];
        float4 b = H[s1 * 16 + c];
        acc.x += a.x; acc.y += a.y; acc.z += a.z; acc.w += a.w;
        acc.x += b.x; acc.y += b.y; acc.z += b.z; acc.w += b.w;
    }
    if (e < eend) {
        int s0 = g_perm[e];
        float4 a = H[s0 * 16 + c];
        acc.x += a.x; acc.y += a.y; acc.z += a.z; acc.w += a.w;
    }
    float nm = g_norm[n];
    ((float4*)g_S2n)[n * 16 + c] =
        make_float4(acc.x * nm, acc.y * nm, acc.z * nm, acc.w * nm);
}

// ================= HMMA (mma.sync) GEMM with bf16 hi/lo split =============
// grid (GTILES, 3); block 64 threads (2 warps). Tile: 64 nodes x 64 outs.
// Warp w: rows w*32 .. w*32+31.
// SMEM bf16 layout, row stride 66 (33 words) for conflict-free fragment LDS.

__device__ __forceinline__ void mma16816(float* c, const uint32_t* a,
                                         uint32_t b0, uint32_t b1) {
    asm volatile(
        "mma.sync.aligned.m16n8k16.row.col.f32.bf16.bf16.f32 "
        "{%0,%1,%2,%3}, {%4,%5,%6,%7}, {%8,%9}, {%0,%1,%2,%3};"
        : "+f"(c[0]), "+f"(c[1]), "+f"(c[2]), "+f"(c[3])
        : "r"(a[0]), "r"(a[1]), "r"(a[2]), "r"(a[3]), "r"(b0), "r"(b1));
}

__device__ __forceinline__ uint32_t pack_bf16(float a, float b) {
    __nv_bfloat162 t = __floats2bfloat162_rn(a, b);   // x=a(low), y=b(high)
    return *reinterpret_cast<uint32_t*>(&t);
}

#define ASTRIDE 33   // words per row (66 bf16)

__global__ __launch_bounds__(64) void gemm_tc_kernel(
    const float* __restrict__ feats,
    const float* __restrict__ w0,
    const float* __restrict__ w1,
    const float* __restrict__ w2,
    float* __restrict__ out) {
    __shared__ __align__(16) uint32_t sAhi[64 * ASTRIDE];
    __shared__ __align__(16) uint32_t sAlo[64 * ASTRIDE];
    __shared__ __align__(16) uint32_t sBhi[64 * ASTRIDE];   // Wt[n][k]
    __shared__ __align__(16) uint32_t sBlo[64 * ASTRIDE];

    int tid = threadIdx.x;
    int w = tid >> 5, lane = tid & 31;
    int g = lane >> 2, q = lane & 3;
    int m = blockIdx.y;
    int rowbase = blockIdx.x * 64;

    // ---- stage A: one row per thread, f32 -> bf16 hi/lo
    const float* srcp = (m == 0) ? feats : (m == 1) ? g_S1n : g_S2n;
    {
        int grow = rowbase + tid;
        if (grow < N_NODES) {
            const float4* rp = (const float4*)(srcp + (size_t)grow * 64);
#pragma unroll
            for (int i = 0; i < 16; i++) {
                float4 v = rp[i];
                float h0 = __bfloat162float(__float2bfloat16_rn(v.x));
                float h1 = __bfloat162float(__float2bfloat16_rn(v.y));
                float h2 = __bfloat162float(__float2bfloat16_rn(v.z));
                float h3 = __bfloat162float(__float2bfloat16_rn(v.w));
                sAhi[tid * ASTRIDE + 2 * i + 0] = pack_bf16(h0, h1);
                sAhi[tid * ASTRIDE + 2 * i + 1] = pack_bf16(h2, h3);
                sAlo[tid * ASTRIDE + 2 * i + 0] = pack_bf16(v.x - h0, v.y - h1);
                sAlo[tid * ASTRIDE + 2 * i + 1] = pack_bf16(v.z - h2, v.w - h3);
            }
        } else {
#pragma unroll
            for (int i = 0; i < 32; i++) {
                sAhi[tid * ASTRIDE + i] = 0;
                sAlo[tid * ASTRIDE + i] = 0;
            }
        }
    }

    // ---- stage B: Wt[n][k] bf16 hi/lo (W is [k][n] row-major f32)
    {
        const float* W = (m == 0) ? w0 : (m == 1) ? w1 : w2;
        __nv_bfloat16* bh = (__nv_bfloat16*)sBhi;
        __nv_bfloat16* bl = (__nv_bfloat16*)sBlo;
#pragma unroll
        for (int i = 0; i < 64; i++) {
            int idx = tid + i * 64;          // idx = k*64 + n
            float v = W[idx];
            int k = idx >> 6, n = idx & 63;
            float h = __bfloat162float(__float2bfloat16_rn(v));
            bh[n * 66 + k] = __float2bfloat16_rn(v);
            bl[n * 66 + k] = __float2bfloat16_rn(v - h);
        }
    }
    __syncthreads();

    // ---- MMA mainloop
    float acc[2][8][4];
#pragma unroll
    for (int mt = 0; mt < 2; mt++)
#pragma unroll
        for (int nt = 0; nt < 8; nt++)
#pragma unroll
            for (int i = 0; i < 4; i++) acc[mt][nt][i] = 0.f;

#pragma unroll
    for (int ks = 0; ks < 4; ks++) {
        uint32_t bh[8][2], bl[8][2];
#pragma unroll
        for (int nt = 0; nt < 8; nt++) {
            int n = nt * 8 + g;
            int bw = n * ASTRIDE + q + ks * 8;
            bh[nt][0] = sBhi[bw];     bh[nt][1] = sBhi[bw + 4];
            bl[nt][0] = sBlo[bw];     bl[nt][1] = sBlo[bw + 4];
        }
#pragma unroll
        for (int mt = 0; mt < 2; mt++) {
            int r0 = w * 32 + mt * 16 + g;
            int aw0 = r0 * ASTRIDE + q + ks * 8;
            int aw1 = (r0 + 8) * ASTRIDE + q + ks * 8;
            uint32_t ahi[4] = {sAhi[aw0], sAhi[aw1], sAhi[aw0 + 4], sAhi[aw1 + 4]};
            uint32_t alo[4] = {sAlo[aw0], sAlo[aw1], sAlo[aw0 + 4], sAlo[aw1 + 4]};
#pragma unroll
            for (int nt = 0; nt < 8; nt++) {
                mma16816(acc[mt][nt], ahi, bh[nt][0], bh[nt][1]);
                mma16816(acc[mt][nt], ahi, bl[nt][0], bl[nt][1]);
                mma16816(acc[mt][nt], alo, bh[nt][0], bh[nt][1]);
            }
        }
    }

    // ---- epilogue
#pragma unroll
    for (int mt = 0; mt < 2; mt++) {
        int r0 = rowbase + w * 32 + mt * 16 + g;
#pragma unroll
        for (int nt = 0; nt < 8; nt++) {
            int col = m * 64 + nt * 8 + q * 2;
            if (r0 < N_NODES)
                *(float2*)(out + (size_t)r0 * 192 + col) =
                    make_float2(acc[mt][nt][0], acc[mt][nt][1]);
            if (r0 + 8 < N_NODES)
                *(float2*)(out + (size_t)(r0 + 8) * 192 + col) =
                    make_float2(acc[mt][nt][2], acc[mt][nt][3]);
        }
    }
}

extern "C" void kernel_launch(void* const* d_in, const int* in_sizes, int n_in,
                              void* d_out, int out_size) {
    const float* feats       = (const float*)d_in[0];
    const float* edge_weight = (const float*)d_in[1];
    const float* w0          = (const float*)d_in[2];
    const float* w1          = (const float*)d_in[3];
    const float* w2          = (const float*)d_in[4];
    const int*   src         = (const int*)d_in[5];
    const int*   dst         = (const int*)d_in[6];
    const int*   e_feat      = (const int*)d_in[7];
    float* out = (float*)d_out;

    zero_kernel<<<(50000 + 255) / 256, 256>>>();
    hist_kernel<<<(N_EDGES + 255) / 256, 256>>>(dst, e_feat, edge_weight);
    scanA_kernel<<<NBLK_SCAN, 256>>>();
    scanC_kernel<<<NBLK_SCAN, 256>>>();
    scatter_kernel<<<(N_EDGES + 255) / 256, 256>>>(src, dst);
    norm_hs0_kernel<<<(N_NODES * 16) / 256, 256>>>(feats);
    gather1_kernel<<<(N_NODES * 16) / 256, 256>>>();
    gather2_kernel<<<(N_NODES * 16) / 256, 256>>>();
    gemm_tc_kernel<<<dim3(GTILES, 3), 64>>>(feats, w0, w1, w2, out);
}